// round 9
// baseline (speedup 1.0000x reference)
#include <cuda_runtime.h>
#include <cuda_bf16.h>

#define G_SIZE 4096
#define B_SIZE 16
#define NCH 15
#define D_MAX 26          // Taylor degree: terms d = 0..26
#define ND (D_MAX + 1)    // 27
#define NSPL 8
#define LPER (G_SIZE / NSPL)   // 512

// Device scratch
__device__ float Mo_part[NSPL * NCH * ND * B_SIZE];   // split partial moments (coef-scaled)

#define LOG2E 1.4426950408889634f

__device__ __forceinline__ float ex2f(float x) {
    float r; asm("ex2.approx.ftz.f32 %0, %1;" : "=f"(r) : "f"(x)); return r;
}
__device__ __forceinline__ unsigned long long pack2(float lo, float hi) {
    unsigned long long r; asm("mov.b64 %0, {%1, %2};" : "=l"(r) : "f"(lo), "f"(hi)); return r;
}
__device__ __forceinline__ void unpack2(unsigned long long v, float &lo, float &hi) {
    asm("mov.b64 {%0, %1}, %2;" : "=f"(lo), "=f"(hi) : "l"(v));
}
// d = d + a*b
__device__ __forceinline__ void fma2(unsigned long long &d, unsigned long long a, unsigned long long b) {
    asm("fma.rn.f32x2 %0, %1, %2, %0;" : "+l"(d) : "l"(a), "l"(b));
}
// d = d*b + c   (Horner form)
__device__ __forceinline__ void fmah2(unsigned long long &d, unsigned long long b, unsigned long long c) {
    asm("fma.rn.f32x2 %0, %0, %1, %2;" : "+l"(d) : "l"(b), "l"(c));
}
__device__ __forceinline__ unsigned long long add2(unsigned long long a, unsigned long long b) {
    unsigned long long r; asm("add.rn.f32x2 %0, %1, %2;" : "=l"(r) : "l"(a), "l"(b)); return r;
}

// gl^e by binary exponentiation (e uniform across CTA -> no divergence)
__device__ __forceinline__ float powu(float g, int e) {
    float p = 1.0f, b = g;
#pragma unroll
    for (int k = 0; k < 5; ++k) {            // e <= 26 < 32
        if (e & 1) p *= b;
        b *= b;
        e >>= 1;
    }
    return p;
}

// Moments partials, on-the-fly F/GP generation, f32x2 inner product.
// Mo_part[s][c][d][b] = coef_d * sum_{l in split s} density[b,l]*gw[l]*exp(-gl^2 xi)*gl^d
// grid = (9 degree-groups, 15 channels, 8 l-splits), 256 threads (8 warps x 2 b)
__global__ __launch_bounds__(256) void moments_kernel(const float* __restrict__ xi,
                                                      const float* __restrict__ grid,
                                                      const float* __restrict__ gw,
                                                      const float* __restrict__ density) {
    __shared__ __align__(16) float prod[3][LPER];      // 6 KB
    const int dg = blockIdx.x;      // 0..8 -> degrees 3dg..3dg+2
    const int c  = blockIdx.y;
    const int sp = blockIdx.z;      // 0..7
    const int tid = threadIdx.x;
    const int l0 = sp * LPER;

    const float xi_t = 1.0f + ex2f(-xi[c] * LOG2E);
    const float cg = -xi_t * LOG2E;
    const int e0 = 3 * dg;

    // Stage: each of 256 threads builds 2 l-entries for all 3 degree rows
    {
        float2 g2 = ((const float2*)(grid + l0))[tid];
        float2 w2 = ((const float2*)(gw + l0))[tid];
        float2 r0, r1, r2;
        {
            float g = g2.x, F = w2.x * ex2f(g * g * cg), p = powu(g, e0);
            r0.x = F * p; p *= g; r1.x = F * p; p *= g; r2.x = F * p;
        }
        {
            float g = g2.y, F = w2.y * ex2f(g * g * cg), p = powu(g, e0);
            r0.y = F * p; p *= g; r1.y = F * p; p *= g; r2.y = F * p;
        }
        ((float2*)prod[0])[tid] = r0;
        ((float2*)prod[1])[tid] = r1;
        ((float2*)prod[2])[tid] = r2;
    }
    __syncthreads();

    const int wid = tid >> 5, lane = tid & 31;

    float t = 2.0f * xi_t;
    float coef0 = 1.0f;
    for (int i = 1; i <= e0; ++i) coef0 = coef0 * t / (float)i;
    float coef1 = coef0 * t / (float)(e0 + 1);
    float coef2 = coef1 * t / (float)(e0 + 2);

    const ulonglong2* p0 = (const ulonglong2*)prod[0];
    const ulonglong2* p1 = (const ulonglong2*)prod[1];
    const ulonglong2* p2 = (const ulonglong2*)prod[2];

    float* Mo = Mo_part + ((sp * NCH + c) * ND + e0) * B_SIZE;

#pragma unroll
    for (int bb = 0; bb < 2; ++bb) {
        int b = 2 * wid + bb;
        const ulonglong2* dr = (const ulonglong2*)(density + b * G_SIZE + l0);
        unsigned long long S0 = 0, U0 = 0, S1 = 0, U1 = 0, S2 = 0, U2 = 0;
#pragma unroll
        for (int i = 0; i < LPER / 4 / 32; ++i) {      // 4 iters, fully unrolled
            int ix = lane + i * 32;
            ulonglong2 d4 = dr[ix];
            ulonglong2 a0 = p0[ix], a1 = p1[ix], a2 = p2[ix];
            fma2(S0, d4.x, a0.x); fma2(U0, d4.y, a0.y);
            fma2(S1, d4.x, a1.x); fma2(U1, d4.y, a1.y);
            fma2(S2, d4.x, a2.x); fma2(U2, d4.y, a2.y);
        }
        float s0, s1, s2, lo, hi;
        S0 = add2(S0, U0); unpack2(S0, lo, hi); s0 = lo + hi;
        S1 = add2(S1, U1); unpack2(S1, lo, hi); s1 = lo + hi;
        S2 = add2(S2, U2); unpack2(S2, lo, hi); s2 = lo + hi;
#pragma unroll
        for (int o = 16; o; o >>= 1) {
            s0 += __shfl_xor_sync(0xffffffffu, s0, o);
            s1 += __shfl_xor_sync(0xffffffffu, s1, o);
            s2 += __shfl_xor_sync(0xffffffffu, s2, o);
        }
        if (lane == 0) {
            Mo[0 * B_SIZE + b] = s0 * coef0;
            Mo[1 * B_SIZE + b] = s1 * coef1;
            Mo[2 * B_SIZE + b] = s2 * coef2;
        }
    }
}

// Output: channels 0..14 = scale_c(gm) * Horner(sum-of-partials, gm); channel 15 = raw density.
// f32x2 Horner: 8 packed accumulators over b-pairs. grid = (32 m-blocks, 16 channels), 128 thr.
__global__ __launch_bounds__(128) void output_kernel(const float* __restrict__ xi,
                                                     const float* __restrict__ grid,
                                                     const float* __restrict__ density,
                                                     float* __restrict__ out) {
    const int c = blockIdx.y;
    const int m = blockIdx.x * 128 + threadIdx.x;

    if (c == NCH) {   // raw density channel
#pragma unroll
        for (int b = 0; b < B_SIZE; ++b)
            out[(b * 16 + NCH) * G_SIZE + m] = density[b * G_SIZE + m];
        return;
    }

    __shared__ __align__(16) float sMo[ND * B_SIZE];   // 432 floats
    for (int i = threadIdx.x; i < ND * B_SIZE; i += 128) {
        float s = 0.f;
#pragma unroll
        for (int sp = 0; sp < NSPL; ++sp)
            s += Mo_part[(sp * NCH + c) * ND * B_SIZE + i];
        sMo[i] = s;
    }
    __syncthreads();

    float gm = grid[m];
    float xi_t = 1.0f + ex2f(-xi[c] * LOG2E);
    float scale = 0.5f * xi_t * ex2f(-gm * gm * xi_t * LOG2E);
    unsigned long long gg = pack2(gm, gm);

    unsigned long long acc[8];
    {
        const ulonglong2* row = (const ulonglong2*)(sMo + D_MAX * B_SIZE);
#pragma unroll
        for (int q = 0; q < 4; ++q) {
            ulonglong2 w = row[q];
            acc[2 * q] = w.x; acc[2 * q + 1] = w.y;
        }
    }
#pragma unroll
    for (int d = D_MAX - 1; d >= 0; --d) {
        const ulonglong2* row = (const ulonglong2*)(sMo + d * B_SIZE);
#pragma unroll
        for (int q = 0; q < 4; ++q) {
            ulonglong2 w = row[q];
            fmah2(acc[2 * q],     gg, w.x);
            fmah2(acc[2 * q + 1], gg, w.y);
        }
    }
#pragma unroll
    for (int p = 0; p < 8; ++p) {
        float v0, v1;
        unpack2(acc[p], v0, v1);
        out[((2 * p) * 16 + c) * G_SIZE + m]     = v0 * scale;
        out[((2 * p + 1) * 16 + c) * G_SIZE + m] = v1 * scale;
    }
}

extern "C" void kernel_launch(void* const* d_in, const int* in_sizes, int n_in,
                              void* d_out, int out_size) {
    const float* density = (const float*)d_in[0];  // (16,1,4096)
    const float* xi      = (const float*)d_in[1];  // (15,)
    const float* grid    = (const float*)d_in[2];  // (4096,)
    const float* gw      = (const float*)d_in[3];  // (4096,)
    float* out = (float*)d_out;                    // (16,16,4096)

    moments_kernel<<<dim3(9, NCH, NSPL), 256>>>(xi, grid, gw, density);
    output_kernel<<<dim3(G_SIZE / 128, NCH + 1), 128>>>(xi, grid, density, out);
}

// round 10
// speedup vs baseline: 1.0152x; 1.0152x over previous
#include <cuda_runtime.h>
#include <cuda_bf16.h>

#define G_SIZE 4096
#define B_SIZE 16
#define NCH 15
#define D_MAX 26          // Taylor degree: terms d = 0..26
#define ND (D_MAX + 1)    // 27
#define NSPL 4
#define LPER (G_SIZE / NSPL)   // 1024
#define NCTAS (9 * NCH * NSPL) // 540

// Device scratch
__device__ float Mo_part[NSPL * NCH * ND * B_SIZE];   // split partial moments (coef-scaled)
__device__ unsigned int sync_ct;                      // phase-1 arrival counter
__device__ unsigned int done_ct;                      // exit counter (for replay-safe reset)

#define LOG2E 1.4426950408889634f

__device__ __forceinline__ float ex2f(float x) {
    float r; asm("ex2.approx.ftz.f32 %0, %1;" : "=f"(r) : "f"(x)); return r;
}

// gl^e by binary exponentiation (e uniform across CTA -> no divergence)
__device__ __forceinline__ float powu(float g, int e) {
    float p = 1.0f, b = g;
#pragma unroll
    for (int k = 0; k < 5; ++k) {            // e <= 26 < 32
        if (e & 1) p *= b;
        b *= b;
        e >>= 1;
    }
    return p;
}

// One fused persistent kernel.
// Phase 1 (per CTA = (dg, c, sp)): partial moments, R7-proven config.
// Global sync (all 540 CTAs co-resident: 256 thr, <=64 regs, 12KB smem -> 4 CTAs/SM).
// Phase 2 (CTA flat id u < 256): output tile c = u>>4, mtile = u&15 (256 m per tile).
__global__ __launch_bounds__(256, 4) void fused_kernel(const float* __restrict__ xi,
                                                       const float* __restrict__ grid,
                                                       const float* __restrict__ gw,
                                                       const float* __restrict__ density,
                                                       float* __restrict__ out) {
    __shared__ __align__(16) float prod[3][LPER];      // 12 KB (reused as sMo in phase 2)
    const int dg = blockIdx.x;      // 0..8 -> degrees 3dg..3dg+2
    const int c  = blockIdx.y;
    const int sp = blockIdx.z;      // 0..3
    const int tid = threadIdx.x;
    const int l0 = sp * LPER;

    // ---------------- Phase 1: partial moments ----------------
    {
        const float xi_t = 1.0f + ex2f(-xi[c] * LOG2E);
        const float cg = -xi_t * LOG2E;
        const int e0 = 3 * dg;

        // Stage: each of 256 threads builds 4 l-entries for all 3 degree rows
        {
            float4 g4 = ((const float4*)(grid + l0))[tid];
            float4 w4 = ((const float4*)(gw + l0))[tid];
            float4 r0, r1, r2;
            {
                float g = g4.x, F = w4.x * ex2f(g * g * cg), p = powu(g, e0);
                r0.x = F * p; p *= g; r1.x = F * p; p *= g; r2.x = F * p;
            }
            {
                float g = g4.y, F = w4.y * ex2f(g * g * cg), p = powu(g, e0);
                r0.y = F * p; p *= g; r1.y = F * p; p *= g; r2.y = F * p;
            }
            {
                float g = g4.z, F = w4.z * ex2f(g * g * cg), p = powu(g, e0);
                r0.z = F * p; p *= g; r1.z = F * p; p *= g; r2.z = F * p;
            }
            {
                float g = g4.w, F = w4.w * ex2f(g * g * cg), p = powu(g, e0);
                r0.w = F * p; p *= g; r1.w = F * p; p *= g; r2.w = F * p;
            }
            ((float4*)prod[0])[tid] = r0;
            ((float4*)prod[1])[tid] = r1;
            ((float4*)prod[2])[tid] = r2;
        }
        __syncthreads();

        const int wid = tid >> 5, lane = tid & 31;

        float t = 2.0f * xi_t;
        float coef0 = 1.0f;
        for (int i = 1; i <= e0; ++i) coef0 = coef0 * t / (float)i;
        float coef1 = coef0 * t / (float)(e0 + 1);
        float coef2 = coef1 * t / (float)(e0 + 2);

        const float4* p0 = (const float4*)prod[0];
        const float4* p1 = (const float4*)prod[1];
        const float4* p2 = (const float4*)prod[2];

        float* Mo = Mo_part + ((sp * NCH + c) * ND + e0) * B_SIZE;

#pragma unroll
        for (int bb = 0; bb < 2; ++bb) {
            int b = 2 * wid + bb;
            const float4* dr = (const float4*)(density + b * G_SIZE + l0);
            float s0 = 0.f, s1 = 0.f, s2 = 0.f;
            float u0 = 0.f, u1 = 0.f, u2 = 0.f;
#pragma unroll
            for (int i = 0; i < LPER / 4 / 32; ++i) {      // 8 iters
                int ix = lane + i * 32;
                float4 d4 = dr[ix];
                float4 a0 = p0[ix], a1 = p1[ix], a2 = p2[ix];
                s0 += d4.x * a0.x + d4.y * a0.y;
                u0 += d4.z * a0.z + d4.w * a0.w;
                s1 += d4.x * a1.x + d4.y * a1.y;
                u1 += d4.z * a1.z + d4.w * a1.w;
                s2 += d4.x * a2.x + d4.y * a2.y;
                u2 += d4.z * a2.z + d4.w * a2.w;
            }
            s0 += u0; s1 += u1; s2 += u2;
#pragma unroll
            for (int o = 16; o; o >>= 1) {
                s0 += __shfl_xor_sync(0xffffffffu, s0, o);
                s1 += __shfl_xor_sync(0xffffffffu, s1, o);
                s2 += __shfl_xor_sync(0xffffffffu, s2, o);
            }
            if (lane == 0) {
                Mo[0 * B_SIZE + b] = s0 * coef0;
                Mo[1 * B_SIZE + b] = s1 * coef1;
                Mo[2 * B_SIZE + b] = s2 * coef2;
            }
        }
    }

    // ---------------- Device-wide sync ----------------
    __syncthreads();
    if (tid == 0) {
        __threadfence();                       // publish Mo_part
        atomicAdd(&sync_ct, 1u);
        while (*((volatile unsigned int*)&sync_ct) < NCTAS) { }
        __threadfence();                       // acquire
    }
    __syncthreads();

    // ---------------- Phase 2: output ----------------
    const int u = blockIdx.x + 9 * (blockIdx.y + NCH * blockIdx.z);  // 0..539
    if (u < 256) {
        const int oc = u >> 4;                 // output channel 0..15
        const int m = (u & 15) * 256 + tid;

        if (oc == NCH) {                       // raw density channel
#pragma unroll
            for (int b = 0; b < B_SIZE; ++b)
                out[(b * 16 + NCH) * G_SIZE + m] = density[b * G_SIZE + m];
        } else {
            float* sMo = prod[0];              // reuse smem (432 floats)
            for (int i = tid; i < ND * B_SIZE; i += 256) {
                float s = 0.f;
#pragma unroll
                for (int spp = 0; spp < NSPL; ++spp)
                    s += Mo_part[(spp * NCH + oc) * ND * B_SIZE + i];
                sMo[i] = s;
            }
            __syncthreads();

            float gm = grid[m];
            float xi_t = 1.0f + ex2f(-xi[oc] * LOG2E);
            float scale = 0.5f * xi_t * ex2f(-gm * gm * xi_t * LOG2E);

            float acc[B_SIZE];
#pragma unroll
            for (int b = 0; b < B_SIZE; ++b)
                acc[b] = sMo[D_MAX * B_SIZE + b];
#pragma unroll
            for (int d = D_MAX - 1; d >= 0; --d) {
#pragma unroll
                for (int b = 0; b < B_SIZE; ++b)
                    acc[b] = acc[b] * gm + sMo[d * B_SIZE + b];
            }
#pragma unroll
            for (int b = 0; b < B_SIZE; ++b)
                out[(b * 16 + oc) * G_SIZE + m] = acc[b] * scale;
        }
    }

    // ---------------- Replay-safe counter reset ----------------
    __syncthreads();
    if (tid == 0) {
        __threadfence();
        unsigned int old = atomicAdd(&done_ct, 1u);
        if (old == NCTAS - 1) {                // last CTA out: nobody reads counters anymore
            sync_ct = 0u;
            done_ct = 0u;
            __threadfence();
        }
    }
}

extern "C" void kernel_launch(void* const* d_in, const int* in_sizes, int n_in,
                              void* d_out, int out_size) {
    const float* density = (const float*)d_in[0];  // (16,1,4096)
    const float* xi      = (const float*)d_in[1];  // (15,)
    const float* grid    = (const float*)d_in[2];  // (4096,)
    const float* gw      = (const float*)d_in[3];  // (4096,)
    float* out = (float*)d_out;                    // (16,16,4096)

    fused_kernel<<<dim3(9, NCH, NSPL), 256>>>(xi, grid, gw, density, out);
}

// round 11
// speedup vs baseline: 1.1552x; 1.1379x over previous
#include <cuda_runtime.h>
#include <cuda_bf16.h>

#define G_SIZE 4096
#define B_SIZE 16
#define NCH 15
#define D_MAX 26          // Taylor degree: terms d = 0..26
#define ND (D_MAX + 1)    // 27
#define NSPL 4
#define LPER (G_SIZE / NSPL)   // 1024

// Device scratch
__device__ float Mo_part[NSPL * NCH * ND * B_SIZE];   // split partial moments (coef-scaled)

#define LOG2E 1.4426950408889634f

__device__ __forceinline__ float ex2f(float x) {
    float r; asm("ex2.approx.ftz.f32 %0, %1;" : "=f"(r) : "f"(x)); return r;
}

// gl^e by binary exponentiation (e uniform across CTA -> no divergence)
__device__ __forceinline__ float powu(float g, int e) {
    float p = 1.0f, b = g;
#pragma unroll
    for (int k = 0; k < 5; ++k) {            // e <= 26 < 32
        if (e & 1) p *= b;
        b *= b;
        e >>= 1;
    }
    return p;
}

// Moments partials (R7-proven config, untouched).
// Mo_part[s][c][d][b] = coef_d * sum_{l in split s} density[b,l]*gw[l]*exp(-gl^2 xi)*gl^d
// grid = (9 degree-groups, 15 channels, 4 l-splits), 256 threads (8 warps x 2 b)
__global__ __launch_bounds__(256) void moments_kernel(const float* __restrict__ xi,
                                                      const float* __restrict__ grid,
                                                      const float* __restrict__ gw,
                                                      const float* __restrict__ density) {
    __shared__ __align__(16) float prod[3][LPER];      // 12 KB
    const int dg = blockIdx.x;      // 0..8 -> degrees 3dg..3dg+2
    const int c  = blockIdx.y;
    const int sp = blockIdx.z;      // 0..3
    const int tid = threadIdx.x;
    const int l0 = sp * LPER;

    const float xi_t = 1.0f + ex2f(-xi[c] * LOG2E);
    const float cg = -xi_t * LOG2E;
    const int e0 = 3 * dg;

    // Stage: each thread builds 4 l-entries for all 3 degree rows
    {
        float4 g4 = ((const float4*)(grid + l0))[tid];
        float4 w4 = ((const float4*)(gw + l0))[tid];
        float4 r0, r1, r2;
        {
            float g = g4.x, F = w4.x * ex2f(g * g * cg), p = powu(g, e0);
            r0.x = F * p; p *= g; r1.x = F * p; p *= g; r2.x = F * p;
        }
        {
            float g = g4.y, F = w4.y * ex2f(g * g * cg), p = powu(g, e0);
            r0.y = F * p; p *= g; r1.y = F * p; p *= g; r2.y = F * p;
        }
        {
            float g = g4.z, F = w4.z * ex2f(g * g * cg), p = powu(g, e0);
            r0.z = F * p; p *= g; r1.z = F * p; p *= g; r2.z = F * p;
        }
        {
            float g = g4.w, F = w4.w * ex2f(g * g * cg), p = powu(g, e0);
            r0.w = F * p; p *= g; r1.w = F * p; p *= g; r2.w = F * p;
        }
        ((float4*)prod[0])[tid] = r0;
        ((float4*)prod[1])[tid] = r1;
        ((float4*)prod[2])[tid] = r2;
    }
    __syncthreads();

    const int wid = tid >> 5, lane = tid & 31;

    float t = 2.0f * xi_t;
    float coef0 = 1.0f;
    for (int i = 1; i <= e0; ++i) coef0 = coef0 * t / (float)i;
    float coef1 = coef0 * t / (float)(e0 + 1);
    float coef2 = coef1 * t / (float)(e0 + 2);

    const float4* p0 = (const float4*)prod[0];
    const float4* p1 = (const float4*)prod[1];
    const float4* p2 = (const float4*)prod[2];

    float* Mo = Mo_part + ((sp * NCH + c) * ND + e0) * B_SIZE;

#pragma unroll
    for (int bb = 0; bb < 2; ++bb) {
        int b = 2 * wid + bb;
        const float4* dr = (const float4*)(density + b * G_SIZE + l0);
        float s0 = 0.f, s1 = 0.f, s2 = 0.f;
        float u0 = 0.f, u1 = 0.f, u2 = 0.f;
#pragma unroll
        for (int i = 0; i < LPER / 4 / 32; ++i) {      // 8 iters, fully unrolled
            int ix = lane + i * 32;
            float4 d4 = dr[ix];
            float4 a0 = p0[ix], a1 = p1[ix], a2 = p2[ix];
            s0 += d4.x * a0.x + d4.y * a0.y;
            u0 += d4.z * a0.z + d4.w * a0.w;
            s1 += d4.x * a1.x + d4.y * a1.y;
            u1 += d4.z * a1.z + d4.w * a1.w;
            s2 += d4.x * a2.x + d4.y * a2.y;
            u2 += d4.z * a2.z + d4.w * a2.w;
        }
        s0 += u0; s1 += u1; s2 += u2;
#pragma unroll
        for (int o = 16; o; o >>= 1) {
            s0 += __shfl_xor_sync(0xffffffffu, s0, o);
            s1 += __shfl_xor_sync(0xffffffffu, s1, o);
            s2 += __shfl_xor_sync(0xffffffffu, s2, o);
        }
        if (lane == 0) {
            Mo[0 * B_SIZE + b] = s0 * coef0;
            Mo[1 * B_SIZE + b] = s1 * coef1;
            Mo[2 * B_SIZE + b] = s2 * coef2;
        }
    }
}

// Output, re-tiled: each thread owns ONE m and FOUR batches (4 short Horner chains).
// grid = (64 m-blocks, 16 channels), 256 threads: tid -> bg = tid>>6 (batch group),
// mi = tid&63, m = blockIdx.x*64 + mi. Channel 15 = raw density copy.
__global__ __launch_bounds__(256) void output_kernel(const float* __restrict__ xi,
                                                     const float* __restrict__ grid,
                                                     const float* __restrict__ density,
                                                     float* __restrict__ out) {
    const int c = blockIdx.y;
    const int tid = threadIdx.x;
    const int bg = tid >> 6;          // 0..3 -> batches 4*bg..4*bg+3
    const int m = blockIdx.x * 64 + (tid & 63);

    if (c == NCH) {   // raw density channel
#pragma unroll
        for (int q = 0; q < 4; ++q) {
            int b = 4 * bg + q;
            out[(b * 16 + NCH) * G_SIZE + m] = density[b * G_SIZE + m];
        }
        return;
    }

    __shared__ __align__(16) float sMo[ND * B_SIZE];   // 432 floats
    for (int i = tid; i < ND * B_SIZE; i += 256) {
        float s = 0.f;
#pragma unroll
        for (int sp = 0; sp < NSPL; ++sp)
            s += Mo_part[(sp * NCH + c) * ND * B_SIZE + i];
        sMo[i] = s;
    }
    __syncthreads();

    float gm = grid[m];
    float xi_t = 1.0f + ex2f(-xi[c] * LOG2E);
    float scale = 0.5f * xi_t * ex2f(-gm * gm * xi_t * LOG2E);

    // 4 independent Horner chains; one broadcast LDS.128 per degree step.
    const float4* col = (const float4*)(sMo) + bg;     // row d -> col[d*4]
    float4 w = col[D_MAX * 4];
    float a0 = w.x, a1 = w.y, a2 = w.z, a3 = w.w;
#pragma unroll
    for (int d = D_MAX - 1; d >= 0; --d) {
        float4 v = col[d * 4];
        a0 = a0 * gm + v.x;
        a1 = a1 * gm + v.y;
        a2 = a2 * gm + v.z;
        a3 = a3 * gm + v.w;
    }

    const int b0 = 4 * bg;
    out[((b0 + 0) * 16 + c) * G_SIZE + m] = a0 * scale;
    out[((b0 + 1) * 16 + c) * G_SIZE + m] = a1 * scale;
    out[((b0 + 2) * 16 + c) * G_SIZE + m] = a2 * scale;
    out[((b0 + 3) * 16 + c) * G_SIZE + m] = a3 * scale;
}

extern "C" void kernel_launch(void* const* d_in, const int* in_sizes, int n_in,
                              void* d_out, int out_size) {
    const float* density = (const float*)d_in[0];  // (16,1,4096)
    const float* xi      = (const float*)d_in[1];  // (15,)
    const float* grid    = (const float*)d_in[2];  // (4096,)
    const float* gw      = (const float*)d_in[3];  // (4096,)
    float* out = (float*)d_out;                    // (16,16,4096)

    moments_kernel<<<dim3(9, NCH, NSPL), 256>>>(xi, grid, gw, density);
    output_kernel<<<dim3(G_SIZE / 64, NCH + 1), 256>>>(xi, grid, density, out);
}

// round 12
// speedup vs baseline: 1.3434x; 1.1629x over previous
#include <cuda_runtime.h>
#include <cuda_bf16.h>

#define G_SIZE 4096
#define B_SIZE 16
#define NCH 15
#define D_MAX 20          // Taylor degree: terms d = 0..20 (tail rel err ~3e-5, all-positive)
#define ND (D_MAX + 1)    // 21
#define NDG (ND / 3)      // 7 degree-groups of 3
#define NSPL 4
#define LPER (G_SIZE / NSPL)   // 1024

// Split-innermost layout: Mo_part[((c*ND + d)*B_SIZE + b)*NSPL + sp]
__device__ float Mo_part[NCH * ND * B_SIZE * NSPL];

#define LOG2E 1.4426950408889634f

__device__ __forceinline__ float ex2f(float x) {
    float r; asm("ex2.approx.ftz.f32 %0, %1;" : "=f"(r) : "f"(x)); return r;
}

// gl^e by binary exponentiation (e uniform across CTA -> no divergence)
__device__ __forceinline__ float powu(float g, int e) {
    float p = 1.0f, b = g;
#pragma unroll
    for (int k = 0; k < 5; ++k) {            // e <= 20 < 32
        if (e & 1) p *= b;
        b *= b;
        e >>= 1;
    }
    return p;
}

// Moments partials (R7-proven inner config; ND=21, split-packed stores).
// grid = (7 degree-groups, 15 channels, 4 l-splits), 256 threads (8 warps x 2 b)
__global__ __launch_bounds__(256) void moments_kernel(const float* __restrict__ xi,
                                                      const float* __restrict__ grid,
                                                      const float* __restrict__ gw,
                                                      const float* __restrict__ density) {
    __shared__ __align__(16) float prod[3][LPER];      // 12 KB
    const int dg = blockIdx.x;      // 0..6 -> degrees 3dg..3dg+2
    const int c  = blockIdx.y;
    const int sp = blockIdx.z;      // 0..3
    const int tid = threadIdx.x;
    const int l0 = sp * LPER;

    const float xi_t = 1.0f + ex2f(-xi[c] * LOG2E);
    const float cg = -xi_t * LOG2E;
    const int e0 = 3 * dg;

    // Stage: each thread builds 4 l-entries for all 3 degree rows
    {
        float4 g4 = ((const float4*)(grid + l0))[tid];
        float4 w4 = ((const float4*)(gw + l0))[tid];
        float4 r0, r1, r2;
        {
            float g = g4.x, F = w4.x * ex2f(g * g * cg), p = powu(g, e0);
            r0.x = F * p; p *= g; r1.x = F * p; p *= g; r2.x = F * p;
        }
        {
            float g = g4.y, F = w4.y * ex2f(g * g * cg), p = powu(g, e0);
            r0.y = F * p; p *= g; r1.y = F * p; p *= g; r2.y = F * p;
        }
        {
            float g = g4.z, F = w4.z * ex2f(g * g * cg), p = powu(g, e0);
            r0.z = F * p; p *= g; r1.z = F * p; p *= g; r2.z = F * p;
        }
        {
            float g = g4.w, F = w4.w * ex2f(g * g * cg), p = powu(g, e0);
            r0.w = F * p; p *= g; r1.w = F * p; p *= g; r2.w = F * p;
        }
        ((float4*)prod[0])[tid] = r0;
        ((float4*)prod[1])[tid] = r1;
        ((float4*)prod[2])[tid] = r2;
    }
    __syncthreads();

    const int wid = tid >> 5, lane = tid & 31;

    float t = 2.0f * xi_t;
    float coef0 = 1.0f;
    for (int i = 1; i <= e0; ++i) coef0 = coef0 * t / (float)i;
    float coef1 = coef0 * t / (float)(e0 + 1);
    float coef2 = coef1 * t / (float)(e0 + 2);

    const float4* p0 = (const float4*)prod[0];
    const float4* p1 = (const float4*)prod[1];
    const float4* p2 = (const float4*)prod[2];

#pragma unroll
    for (int bb = 0; bb < 2; ++bb) {
        int b = 2 * wid + bb;
        const float4* dr = (const float4*)(density + b * G_SIZE + l0);
        float s0 = 0.f, s1 = 0.f, s2 = 0.f;
        float u0 = 0.f, u1 = 0.f, u2 = 0.f;
#pragma unroll
        for (int i = 0; i < LPER / 4 / 32; ++i) {      // 8 iters, fully unrolled
            int ix = lane + i * 32;
            float4 d4 = dr[ix];
            float4 a0 = p0[ix], a1 = p1[ix], a2 = p2[ix];
            s0 += d4.x * a0.x + d4.y * a0.y;
            u0 += d4.z * a0.z + d4.w * a0.w;
            s1 += d4.x * a1.x + d4.y * a1.y;
            u1 += d4.z * a1.z + d4.w * a1.w;
            s2 += d4.x * a2.x + d4.y * a2.y;
            u2 += d4.z * a2.z + d4.w * a2.w;
        }
        s0 += u0; s1 += u1; s2 += u2;
#pragma unroll
        for (int o = 16; o; o >>= 1) {
            s0 += __shfl_xor_sync(0xffffffffu, s0, o);
            s1 += __shfl_xor_sync(0xffffffffu, s1, o);
            s2 += __shfl_xor_sync(0xffffffffu, s2, o);
        }
        if (lane == 0) {
            Mo_part[((c * ND + e0 + 0) * B_SIZE + b) * NSPL + sp] = s0 * coef0;
            Mo_part[((c * ND + e0 + 1) * B_SIZE + b) * NSPL + sp] = s1 * coef1;
            Mo_part[((c * ND + e0 + 2) * B_SIZE + b) * NSPL + sp] = s2 * coef2;
        }
    }
}

// Output: 512 threads = 4 batch-groups x 128 m. grid = (32 m-blocks, 16 channels).
// Preamble: one float4 LDG per sMo element (4 splits contiguous) + in-reg reduce.
__global__ __launch_bounds__(512) void output_kernel(const float* __restrict__ xi,
                                                     const float* __restrict__ grid,
                                                     const float* __restrict__ density,
                                                     float* __restrict__ out) {
    const int c = blockIdx.y;
    const int tid = threadIdx.x;
    const int bg = tid >> 7;          // 0..3 -> batches 4*bg..4*bg+3
    const int m = blockIdx.x * 128 + (tid & 127);

    if (c == NCH) {   // raw density channel
#pragma unroll
        for (int q = 0; q < 4; ++q) {
            int b = 4 * bg + q;
            out[(b * 16 + NCH) * G_SIZE + m] = density[b * G_SIZE + m];
        }
        return;
    }

    __shared__ __align__(16) float sMo[ND * B_SIZE];   // 336 floats
    if (tid < ND * B_SIZE) {
        float4 v = ((const float4*)Mo_part)[c * ND * B_SIZE + tid];
        sMo[tid] = (v.x + v.y) + (v.z + v.w);
    }
    __syncthreads();

    float gm = grid[m];
    float xi_t = 1.0f + ex2f(-xi[c] * LOG2E);
    float scale = 0.5f * xi_t * ex2f(-gm * gm * xi_t * LOG2E);

    // 4 independent Horner chains; one broadcast LDS.128 per degree step.
    const float4* col = (const float4*)(sMo) + bg;     // row d -> col[d*4]
    float4 w = col[D_MAX * 4];
    float a0 = w.x, a1 = w.y, a2 = w.z, a3 = w.w;
#pragma unroll
    for (int d = D_MAX - 1; d >= 0; --d) {
        float4 v = col[d * 4];
        a0 = a0 * gm + v.x;
        a1 = a1 * gm + v.y;
        a2 = a2 * gm + v.z;
        a3 = a3 * gm + v.w;
    }

    const int b0 = 4 * bg;
    out[((b0 + 0) * 16 + c) * G_SIZE + m] = a0 * scale;
    out[((b0 + 1) * 16 + c) * G_SIZE + m] = a1 * scale;
    out[((b0 + 2) * 16 + c) * G_SIZE + m] = a2 * scale;
    out[((b0 + 3) * 16 + c) * G_SIZE + m] = a3 * scale;
}

extern "C" void kernel_launch(void* const* d_in, const int* in_sizes, int n_in,
                              void* d_out, int out_size) {
    const float* density = (const float*)d_in[0];  // (16,1,4096)
    const float* xi      = (const float*)d_in[1];  // (15,)
    const float* grid    = (const float*)d_in[2];  // (4096,)
    const float* gw      = (const float*)d_in[3];  // (4096,)
    float* out = (float*)d_out;                    // (16,16,4096)

    moments_kernel<<<dim3(NDG, NCH, NSPL), 256>>>(xi, grid, gw, density);
    output_kernel<<<dim3(G_SIZE / 128, NCH + 1), 512>>>(xi, grid, density, out);
}